// round 6
// baseline (speedup 1.0000x reference)
#include <cuda_runtime.h>
#include <cuda_bf16.h>
#include <cstdint>

#define MARGIN 0.5f
#define POS_W 1.0f
#define NEG_W 1.0f

#define R_THREADS 256
#define GRID_BLOCKS 1184   // 148 SMs x 8 blocks (32 regs x 256 thr -> 8 blocks/SM)
#define MAX_B 1024

// Scratch (allocations forbidden; __device__ globals).
// g_batch_sum starts zeroed (static init); the tail block re-zeroes it after
// consuming, so every graph replay sees zeros. Same for g_arrival.
__device__ float g_batch_sum[MAX_B];
__device__ unsigned int g_arrival = 0;

// Reduce a contiguous [seg_base, seg_base+seg_len) float4 range with all 256
// threads; returns block-level sum (valid in all threads of warp 0, lane 0 used).
__device__ __forceinline__ float block_reduce_range(
    const float4* __restrict__ p, int seg_len, float* warp_sums) {
    float a0 = 0.f, a1 = 0.f, a2 = 0.f, a3 = 0.f;
    int i = threadIdx.x;
    const int stride = R_THREADS;
    const int n4 = seg_len - (seg_len % (4 * stride));
    for (; i < n4; i += 4 * stride) {
        float4 v0 = p[i];
        float4 v1 = p[i + stride];
        float4 v2 = p[i + 2 * stride];
        float4 v3 = p[i + 3 * stride];
        a0 += (v0.x + v0.y) + (v0.z + v0.w);
        a1 += (v1.x + v1.y) + (v1.z + v1.w);
        a2 += (v2.x + v2.y) + (v2.z + v2.w);
        a3 += (v3.x + v3.y) + (v3.z + v3.w);
    }
    for (; i < seg_len; i += stride) {
        float4 v = p[i];
        a0 += (v.x + v.y) + (v.z + v.w);
    }
    float acc = (a0 + a1) + (a2 + a3);

    #pragma unroll
    for (int off = 16; off > 0; off >>= 1)
        acc += __shfl_xor_sync(0xFFFFFFFFu, acc, off);

    const int lane = threadIdx.x & 31, wid = threadIdx.x >> 5;
    if (lane == 0) warp_sums[wid] = acc;
    __syncthreads();

    float s = 0.0f;
    if (wid == 0) {
        s = (lane < R_THREADS / 32) ? warp_sums[lane] : 0.0f;
        #pragma unroll
        for (int off = 4; off > 0; off >>= 1)
            s += __shfl_xor_sync(0xFFFFFFFFu, s, off);
    }
    __syncthreads();   // warp_sums reused by caller for second segment
    return s;
}

__global__ __launch_bounds__(R_THREADS, 8) void fused_loss_kernel(
    const float* __restrict__ graph,
    const int* __restrict__ labels,
    float* __restrict__ out,
    int B, int ne_per_batch, int total_vec) {

    const int vec_per_batch = ne_per_batch >> 2;

    // Contiguous range for this block: q or q+1 float4s.
    const int q = total_vec / GRID_BLOCKS;
    const int r = total_vec % GRID_BLOCKS;
    const int bid = blockIdx.x;
    const long long start = (long long)bid * q + min(bid, r);
    const int len = q + (bid < r ? 1 : 0);
    const long long end = start + len;

    const float4* __restrict__ gvec = reinterpret_cast<const float4*>(graph);

    __shared__ float warp_sums[R_THREADS / 32];

    // Range crosses at most one batch boundary (len < vec_per_batch).
    const int batch0 = (int)(start / vec_per_batch);
    const long long b0_end = (long long)(batch0 + 1) * vec_per_batch;
    const int seg0_len = (int)(end <= b0_end ? len : (b0_end - start));

    float s0 = block_reduce_range(gvec + start, seg0_len, warp_sums);
    if (threadIdx.x == 0) atomicAdd(&g_batch_sum[batch0], s0);

    if (seg0_len < len) {
        const int seg1_len = len - seg0_len;
        float s1 = block_reduce_range(gvec + start + seg0_len, seg1_len, warp_sums);
        if (threadIdx.x == 0) atomicAdd(&g_batch_sum[batch0 + 1], s1);
    }

    // Arrival: last block does the tail.
    __shared__ bool is_last;
    if (threadIdx.x == 0) {
        __threadfence();
        unsigned int prev = atomicAdd(&g_arrival, 1u);
        is_last = (prev == gridDim.x - 1);
    }
    __syncthreads();
    if (!is_last) return;

    // ---- tail: pooled sims + pair loss; then reset scratch for next replay ----
    if (threadIdx.x == 0) g_arrival = 0;

    __shared__ float gs[MAX_B];
    __shared__ int lab[MAX_B];
    const float inv_ne = 1.0f / (float)ne_per_batch;

    for (int t = threadIdx.x; t < B; t += R_THREADS) {
        gs[t] = __ldcg(&g_batch_sum[t]) * inv_ne;   // L2 read (atomics live in L2)
        lab[t] = labels[t];
        g_batch_sum[t] = 0.0f;                      // reset for next replay
    }
    __syncthreads();

    float pacc = 0.0f;
    for (int t = threadIdx.x; t < B; t += R_THREADS) {
        const float gi = gs[t];
        const int li = lab[t];
        for (int j = t + 1; j < B; ++j) {
            const float sim = gi * gs[j];
            const float pos = fmaxf(MARGIN - sim, 0.0f);
            const float neg = fmaxf(sim - (1.0f - MARGIN), 0.0f);
            pacc += (li == lab[j]) ? (POS_W * pos) : (NEG_W * neg);
        }
    }

    #pragma unroll
    for (int off = 16; off > 0; off >>= 1)
        pacc += __shfl_xor_sync(0xFFFFFFFFu, pacc, off);

    const int lane = threadIdx.x & 31, wid = threadIdx.x >> 5;
    __shared__ float pw[R_THREADS / 32];
    if (lane == 0) pw[wid] = pacc;
    __syncthreads();

    if (wid == 0) {
        float s = (lane < R_THREADS / 32) ? pw[lane] : 0.0f;
        #pragma unroll
        for (int off = 4; off > 0; off >>= 1)
            s += __shfl_xor_sync(0xFFFFFFFFu, s, off);
        if (lane == 0) {
            const float num_pairs = 0.5f * (float)B * (float)(B - 1);
            out[0] = s / num_pairs;
        }
    }
}

extern "C" void kernel_launch(void* const* d_in, const int* in_sizes, int n_in,
                              void* d_out, int out_size) {
    const float* graph = (const float*)d_in[0];
    const int* labels = (const int*)d_in[1];
    float* out = (float*)d_out;

    const int total = in_sizes[0];   // B * N * N
    const int B = in_sizes[1];       // 256
    const int ne = total / B;        // N*N = 262144
    const int total_vec = total >> 2;

    fused_loss_kernel<<<GRID_BLOCKS, R_THREADS>>>(graph, labels, out, B, ne, total_vec);
}

// round 7
// speedup vs baseline: 1.2611x; 1.2611x over previous
#include <cuda_runtime.h>
#include <cuda_bf16.h>
#include <cstdint>

#define MARGIN 0.5f
#define POS_W 1.0f
#define NEG_W 1.0f

#define BLOCKS_PER_BATCH 4
#define R_THREADS 256
#define MAX_PARTIALS 8192
#define MAX_B 1024

// Scratch (allocations forbidden; __device__ globals).
// Every g_partial slot used is rewritten each call -> no zeroing needed.
__device__ float g_partial[MAX_PARTIALS];
__device__ unsigned int g_arrival = 0;   // last block resets to 0 each call

__global__ __launch_bounds__(R_THREADS, 8) void fused_loss_kernel(
    const float* __restrict__ graph,
    const int* __restrict__ labels,
    float* __restrict__ out,
    int B, int ne_per_batch) {

    const int b = blockIdx.x / BLOCKS_PER_BATCH;
    const int chunk = blockIdx.x % BLOCKS_PER_BATCH;
    const int vec_per_batch = ne_per_batch >> 2;               // float4 count
    const int vec_per_chunk = vec_per_batch / BLOCKS_PER_BATCH;

    const float4* __restrict__ base =
        reinterpret_cast<const float4*>(graph) +
        (size_t)b * vec_per_batch + (size_t)chunk * vec_per_chunk;

    // 4 independent accumulators, unroll-4; streaming (evict-first) loads
    // since graph is touched exactly once.
    float a0 = 0.0f, a1 = 0.0f, a2 = 0.0f, a3 = 0.0f;
    int i = threadIdx.x;
    const int stride = R_THREADS;
    const int n4 = vec_per_chunk & ~(4 * stride - 1);  // full unroll-4 span
    for (; i < n4; i += 4 * stride) {
        float4 v0 = __ldcs(&base[i]);
        float4 v1 = __ldcs(&base[i + stride]);
        float4 v2 = __ldcs(&base[i + 2 * stride]);
        float4 v3 = __ldcs(&base[i + 3 * stride]);
        a0 += (v0.x + v0.y) + (v0.z + v0.w);
        a1 += (v1.x + v1.y) + (v1.z + v1.w);
        a2 += (v2.x + v2.y) + (v2.z + v2.w);
        a3 += (v3.x + v3.y) + (v3.z + v3.w);
    }
    for (; i < vec_per_chunk; i += stride) {
        float4 v = __ldcs(&base[i]);
        a0 += (v.x + v.y) + (v.z + v.w);
    }
    float acc = (a0 + a1) + (a2 + a3);

    // block reduce
    #pragma unroll
    for (int off = 16; off > 0; off >>= 1)
        acc += __shfl_xor_sync(0xFFFFFFFFu, acc, off);

    __shared__ float warp_sums[R_THREADS / 32];
    const int lane = threadIdx.x & 31, wid = threadIdx.x >> 5;
    if (lane == 0) warp_sums[wid] = acc;
    __syncthreads();

    __shared__ bool is_last;
    if (wid == 0) {
        float s = (lane < R_THREADS / 32) ? warp_sums[lane] : 0.0f;
        #pragma unroll
        for (int off = 4; off > 0; off >>= 1)
            s += __shfl_xor_sync(0xFFFFFFFFu, s, off);
        if (lane == 0) {
            g_partial[blockIdx.x] = s;
            __threadfence();
            unsigned int prev = atomicAdd(&g_arrival, 1u);
            is_last = (prev == gridDim.x - 1);
        }
    }
    __syncthreads();

    if (!is_last) return;

    // ---- tail: last block computes pooled sims + pair loss ----
    if (threadIdx.x == 0) g_arrival = 0;   // reset for next graph replay

    __shared__ float gs[MAX_B];
    __shared__ int lab[MAX_B];
    const float inv_ne = 1.0f / (float)ne_per_batch;

    for (int t = threadIdx.x; t < B; t += R_THREADS) {
        float s = 0.0f;
        #pragma unroll
        for (int c = 0; c < BLOCKS_PER_BATCH; ++c)
            s += g_partial[t * BLOCKS_PER_BATCH + c];
        gs[t] = s * inv_ne;
        lab[t] = labels[t];
    }
    __syncthreads();

    float pacc = 0.0f;
    for (int t = threadIdx.x; t < B; t += R_THREADS) {
        const float gi = gs[t];
        const int li = lab[t];
        for (int j = t + 1; j < B; ++j) {
            const float sim = gi * gs[j];
            const float pos = fmaxf(MARGIN - sim, 0.0f);
            const float neg = fmaxf(sim - (1.0f - MARGIN), 0.0f);
            pacc += (li == lab[j]) ? (POS_W * pos) : (NEG_W * neg);
        }
    }

    #pragma unroll
    for (int off = 16; off > 0; off >>= 1)
        pacc += __shfl_xor_sync(0xFFFFFFFFu, pacc, off);

    __shared__ float pw[R_THREADS / 32];
    if (lane == 0) pw[wid] = pacc;
    __syncthreads();

    if (wid == 0) {
        float s = (lane < R_THREADS / 32) ? pw[lane] : 0.0f;
        #pragma unroll
        for (int off = 4; off > 0; off >>= 1)
            s += __shfl_xor_sync(0xFFFFFFFFu, s, off);
        if (lane == 0) {
            const float num_pairs = 0.5f * (float)B * (float)(B - 1);
            out[0] = s / num_pairs;
        }
    }
}

extern "C" void kernel_launch(void* const* d_in, const int* in_sizes, int n_in,
                              void* d_out, int out_size) {
    const float* graph = (const float*)d_in[0];
    const int* labels = (const int*)d_in[1];
    float* out = (float*)d_out;

    const int total = in_sizes[0];   // B * N * N
    const int B = in_sizes[1];       // 256
    const int ne = total / B;        // N*N = 262144

    fused_loss_kernel<<<B * BLOCKS_PER_BATCH, R_THREADS>>>(graph, labels, out, B, ne);
}